// round 1
// baseline (speedup 1.0000x reference)
#include <cuda_runtime.h>
#include <math.h>

#define NN   50000
#define BB   50
#define NPGc 1000
#define EE   300000
#define HH   256
#define KSEL 500

// ---------------- scratch (static device globals; no allocation) ----------------
__device__ float d_h1[NN * HH];      // layer1 output
__device__ float d_g [NN * HH];      // aggregated h1 (pre-GEMM)
__device__ float d_h [NN * HH];      // layer2 output
__device__ int   d_indeg[NN];
__device__ int   d_rowptr[NN + 1];
__device__ int   d_fill[NN];
__device__ int   d_col[EE];          // CSR: src node per incoming edge, grouped by dst
__device__ float d_dinv[NN];
__device__ float d_r[NN];
__device__ float d_root[NN];
__device__ float d_score[NN];

// ---------------- CSR build ----------------
__global__ void k_zero() {
    int i = blockIdx.x * blockDim.x + threadIdx.x;
    if (i < NN) { d_indeg[i] = 0; d_fill[i] = 0; }
}

__global__ void k_hist(const int* __restrict__ dst) {
    int i = blockIdx.x * blockDim.x + threadIdx.x;
    if (i < EE) atomicAdd(&d_indeg[dst[i]], 1);
}

// single-block exclusive scan (shuffle-based, 3 barriers per 1024-chunk)
__global__ void k_scan() {
    __shared__ int wsum[32];
    __shared__ int carry;
    int t = threadIdx.x, lane = t & 31, wid = t >> 5;
    if (t == 0) carry = 0;
    __syncthreads();
    for (int base = 0; base < NN; base += 1024) {
        int i = base + t;
        int v = (i < NN) ? d_indeg[i] : 0;
        int sv = v;
        #pragma unroll
        for (int off = 1; off < 32; off <<= 1) {
            int n = __shfl_up_sync(0xffffffffu, sv, off);
            if (lane >= off) sv += n;
        }
        if (lane == 31) wsum[wid] = sv;
        __syncthreads();
        if (wid == 0) {
            int w = wsum[lane];
            #pragma unroll
            for (int off = 1; off < 32; off <<= 1) {
                int n = __shfl_up_sync(0xffffffffu, w, off);
                if (lane >= off) w += n;
            }
            wsum[lane] = w;
        }
        __syncthreads();
        int incl = sv + (wid > 0 ? wsum[wid - 1] : 0);
        if (i < NN) {
            d_rowptr[i] = carry + incl - v;            // exclusive
            d_dinv[i]   = rsqrtf((float)(v + 1));      // deg = indeg + self-loop
        }
        int total = wsum[31];
        __syncthreads();
        if (t == 0) carry += total;
        __syncthreads();
    }
    if (t == 0) d_rowptr[NN] = carry;
}

__global__ void k_scatter(const int* __restrict__ src, const int* __restrict__ dst) {
    int i = blockIdx.x * blockDim.x + threadIdx.x;
    if (i < EE) {
        int d = dst[i];
        int p = d_rowptr[d] + atomicAdd(&d_fill[d], 1);
        d_col[p] = src[i];
    }
}

// ---------------- layer 1: fused onehot-gather GCN conv (warp per node) ----------------
__global__ __launch_bounds__(256) void k_layer1(const int* __restrict__ x,
                                                const float* __restrict__ W1,
                                                const float* __restrict__ b1) {
    int node = (blockIdx.x * blockDim.x + threadIdx.x) >> 5;
    int lane = threadIdx.x & 31;
    if (node >= NN) return;
    float dd = d_dinv[node];
    float4 a0, a1;
    {
        const float4* p = (const float4*)(W1 + (size_t)x[node] * HH) + lane * 2;
        float4 v0 = p[0], v1 = p[1];
        a0.x = dd * v0.x; a0.y = dd * v0.y; a0.z = dd * v0.z; a0.w = dd * v0.w;
        a1.x = dd * v1.x; a1.y = dd * v1.y; a1.z = dd * v1.z; a1.w = dd * v1.w;
    }
    int beg = d_rowptr[node], end = d_rowptr[node + 1];
    for (int e = beg; e < end; e++) {
        int s = d_col[e];
        float w = d_dinv[s];
        const float4* p = (const float4*)(W1 + (size_t)x[s] * HH) + lane * 2;
        float4 v0 = p[0], v1 = p[1];
        a0.x += w * v0.x; a0.y += w * v0.y; a0.z += w * v0.z; a0.w += w * v0.w;
        a1.x += w * v1.x; a1.y += w * v1.y; a1.z += w * v1.z; a1.w += w * v1.w;
    }
    const float4* b4 = (const float4*)b1 + lane * 2;
    float4 c0 = b4[0], c1 = b4[1];
    float4 o0, o1;
    o0.x = fmaxf(dd * a0.x + c0.x, 0.f); o0.y = fmaxf(dd * a0.y + c0.y, 0.f);
    o0.z = fmaxf(dd * a0.z + c0.z, 0.f); o0.w = fmaxf(dd * a0.w + c0.w, 0.f);
    o1.x = fmaxf(dd * a1.x + c1.x, 0.f); o1.y = fmaxf(dd * a1.y + c1.y, 0.f);
    o1.z = fmaxf(dd * a1.z + c1.z, 0.f); o1.w = fmaxf(dd * a1.w + c1.w, 0.f);
    float4* outp = (float4*)(d_h1 + (size_t)node * HH) + lane * 2;
    outp[0] = o0; outp[1] = o1;
}

// ---------------- layer 2 aggregation (A-hat * h1), warp per node ----------------
__global__ __launch_bounds__(256) void k_agg() {
    int node = (blockIdx.x * blockDim.x + threadIdx.x) >> 5;
    int lane = threadIdx.x & 31;
    if (node >= NN) return;
    float dd = d_dinv[node];
    float4 a0, a1;
    {
        const float4* p = (const float4*)(d_h1 + (size_t)node * HH) + lane * 2;
        float4 v0 = p[0], v1 = p[1];
        a0.x = dd * v0.x; a0.y = dd * v0.y; a0.z = dd * v0.z; a0.w = dd * v0.w;
        a1.x = dd * v1.x; a1.y = dd * v1.y; a1.z = dd * v1.z; a1.w = dd * v1.w;
    }
    int beg = d_rowptr[node], end = d_rowptr[node + 1];
    for (int e = beg; e < end; e++) {
        int s = d_col[e];
        float w = d_dinv[s];
        const float4* p = (const float4*)(d_h1 + (size_t)s * HH) + lane * 2;
        float4 v0 = p[0], v1 = p[1];
        a0.x += w * v0.x; a0.y += w * v0.y; a0.z += w * v0.z; a0.w += w * v0.w;
        a1.x += w * v1.x; a1.y += w * v1.y; a1.z += w * v1.z; a1.w += w * v1.w;
    }
    float4 o0, o1;
    o0.x = dd * a0.x; o0.y = dd * a0.y; o0.z = dd * a0.z; o0.w = dd * a0.w;
    o1.x = dd * a1.x; o1.y = dd * a1.y; o1.z = dd * a1.z; o1.w = dd * a1.w;
    float4* outp = (float4*)(d_g + (size_t)node * HH) + lane * 2;
    outp[0] = o0; outp[1] = o1;
}

// ---------------- GEMM: h = relu(d_g @ W2 + b2), 64x64 tile, 4x4 microtile ----------------
__global__ __launch_bounds__(256) void k_gemm(const float* __restrict__ W2,
                                              const float* __restrict__ b2) {
    __shared__ __align__(16) float As[16][64];   // [k][row]
    __shared__ __align__(16) float Bs[16][64];   // [k][col]
    int tid = threadIdx.x;
    int tx = tid & 15, ty = tid >> 4;
    int rowBase = blockIdx.x * 64;
    int colBase = blockIdx.y * 64;
    int aRow = tid >> 2, aQ = tid & 3;
    int bK = tid >> 4, bQ = tid & 15;

    float4 acc0 = {0,0,0,0}, acc1 = {0,0,0,0}, acc2 = {0,0,0,0}, acc3 = {0,0,0,0};

    for (int k0 = 0; k0 < HH; k0 += 16) {
        float4 av = {0,0,0,0};
        int gr = rowBase + aRow;
        if (gr < NN) av = *(const float4*)(d_g + (size_t)gr * HH + k0 + aQ * 4);
        As[aQ * 4 + 0][aRow] = av.x;
        As[aQ * 4 + 1][aRow] = av.y;
        As[aQ * 4 + 2][aRow] = av.z;
        As[aQ * 4 + 3][aRow] = av.w;
        *(float4*)&Bs[bK][bQ * 4] =
            *(const float4*)(W2 + (size_t)(k0 + bK) * HH + colBase + bQ * 4);
        __syncthreads();
        #pragma unroll
        for (int kk = 0; kk < 16; kk++) {
            float4 a = *(const float4*)&As[kk][ty * 4];
            float4 b = *(const float4*)&Bs[kk][tx * 4];
            acc0.x += a.x * b.x; acc0.y += a.x * b.y; acc0.z += a.x * b.z; acc0.w += a.x * b.w;
            acc1.x += a.y * b.x; acc1.y += a.y * b.y; acc1.z += a.y * b.z; acc1.w += a.y * b.w;
            acc2.x += a.z * b.x; acc2.y += a.z * b.y; acc2.z += a.z * b.z; acc2.w += a.z * b.w;
            acc3.x += a.w * b.x; acc3.y += a.w * b.y; acc3.z += a.w * b.z; acc3.w += a.w * b.w;
        }
        __syncthreads();
    }
    float4 bias = *(const float4*)(b2 + colBase + tx * 4);
    float4 accs[4] = {acc0, acc1, acc2, acc3};
    #pragma unroll
    for (int i = 0; i < 4; i++) {
        int gr = rowBase + ty * 4 + i;
        if (gr < NN) {
            float4 o;
            o.x = fmaxf(accs[i].x + bias.x, 0.f);
            o.y = fmaxf(accs[i].y + bias.y, 0.f);
            o.z = fmaxf(accs[i].z + bias.z, 0.f);
            o.w = fmaxf(accs[i].w + bias.w, 0.f);
            *(float4*)(d_h + (size_t)gr * HH + colBase + tx * 4) = o;
        }
    }
}

// ---------------- scorer: r = h.Wrel, root = h.Wroot (warp per node) ----------------
__global__ __launch_bounds__(256) void k_rroot(const float* __restrict__ Wrel,
                                               const float* __restrict__ Wroot) {
    int node = (blockIdx.x * blockDim.x + threadIdx.x) >> 5;
    int lane = threadIdx.x & 31;
    if (node >= NN) return;
    const float4* hp = (const float4*)(d_h + (size_t)node * HH) + lane * 2;
    const float4* rp = (const float4*)Wrel + lane * 2;
    const float4* op = (const float4*)Wroot + lane * 2;
    float4 h0 = hp[0], h1 = hp[1];
    float4 r0 = rp[0], r1 = rp[1];
    float4 o0 = op[0], o1 = op[1];
    float pr = h0.x*r0.x + h0.y*r0.y + h0.z*r0.z + h0.w*r0.w
             + h1.x*r1.x + h1.y*r1.y + h1.z*r1.z + h1.w*r1.w;
    float po = h0.x*o0.x + h0.y*o0.y + h0.z*o0.z + h0.w*o0.w
             + h1.x*o1.x + h1.y*o1.y + h1.z*o1.z + h1.w*o1.w;
    #pragma unroll
    for (int off = 16; off > 0; off >>= 1) {
        pr += __shfl_down_sync(0xffffffffu, pr, off);
        po += __shfl_down_sync(0xffffffffu, po, off);
    }
    if (lane == 0) { d_r[node] = pr; d_root[node] = po; }
}

__global__ void k_score(const float* __restrict__ brel) {
    int i = blockIdx.x * blockDim.x + threadIdx.x;
    if (i >= NN) return;
    float sc = brel[0] + d_root[i];
    int beg = d_rowptr[i], end = d_rowptr[i + 1];
    for (int e = beg; e < end; e++) sc += d_r[d_col[e]];
    d_score[i] = sc;
}

// ---------------- per-graph top-K (bitonic sort) + tanh-gated global max pool ----------------
__global__ __launch_bounds__(512) void k_pool(float* __restrict__ out) {
    __shared__ float ss[1024];
    __shared__ int   si[1024];
    __shared__ float red[512];
    int b = blockIdx.x, t = threadIdx.x;
    for (int i = t; i < 1024; i += 512) {
        if (i < NPGc) { ss[i] = d_score[b * NPGc + i]; si[i] = i; }
        else          { ss[i] = -INFINITY;             si[i] = 0x7fffffff; }
    }
    __syncthreads();
    // sort descending by score, ascending index on ties (matches top_k stability)
    for (int k = 2; k <= 1024; k <<= 1) {
        for (int j = k >> 1; j > 0; j >>= 1) {
            #pragma unroll
            for (int half = 0; half < 2; half++) {
                int i = t + half * 512;
                int ixj = i ^ j;
                if (ixj > i) {
                    float s1 = ss[i], s2 = ss[ixj];
                    int   i1 = si[i], i2 = si[ixj];
                    bool up  = ((i & k) == 0);
                    bool b21 = (s2 > s1) || (s2 == s1 && i2 < i1);  // arr[ixj] precedes arr[i]
                    bool b12 = (s1 > s2) || (s1 == s2 && i1 < i2);
                    if (up ? b21 : b12) {
                        ss[i] = s2; ss[ixj] = s1;
                        si[i] = i2; si[ixj] = i1;
                    }
                }
            }
            __syncthreads();
        }
    }
    // tanh gate on selected scores
    for (int i = t; i < KSEL; i += 512) ss[i] = tanhf(ss[i]);
    __syncthreads();
    int part = t >> 8, f = t & 255;
    float m = -INFINITY;
    int j0 = part * (KSEL / 2), j1 = j0 + (KSEL / 2);
    for (int j = j0; j < j1; j++) {
        int node = b * NPGc + si[j];
        m = fmaxf(m, d_h[(size_t)node * HH + f] * ss[j]);
    }
    red[t] = m;
    __syncthreads();
    if (part == 0) out[b * HH + f] = fmaxf(red[t], red[t + 256]);
}

// ---------------- launch ----------------
extern "C" void kernel_launch(void* const* d_in, const int* in_sizes, int n_in,
                              void* d_out, int out_size) {
    const int*   x     = (const int*)d_in[0];
    const int*   ei    = (const int*)d_in[1];
    const float* W1    = (const float*)d_in[3];
    const float* b1    = (const float*)d_in[4];
    const float* W2    = (const float*)d_in[5];
    const float* b2    = (const float*)d_in[6];
    const float* Wrel  = (const float*)d_in[7];
    const float* brel  = (const float*)d_in[8];
    const float* Wroot = (const float*)d_in[9];
    float* out = (float*)d_out;
    const int* src = ei;
    const int* dst = ei + EE;

    k_zero   <<<(NN + 255) / 256, 256>>>();
    k_hist   <<<(EE + 255) / 256, 256>>>(dst);
    k_scan   <<<1, 1024>>>();
    k_scatter<<<(EE + 255) / 256, 256>>>(src, dst);
    k_layer1 <<<(NN + 7) / 8, 256>>>(x, W1, b1);
    k_agg    <<<(NN + 7) / 8, 256>>>();
    k_gemm   <<<dim3((NN + 63) / 64, HH / 64), 256>>>(W2, b2);
    k_rroot  <<<(NN + 7) / 8, 256>>>(Wrel, Wroot);
    k_score  <<<(NN + 255) / 256, 256>>>(brel);
    k_pool   <<<BB, 512>>>(out);
}